// round 17
// baseline (speedup 1.0000x reference)
#include <cuda_runtime.h>
#include <cuda_bf16.h>
#include <cstdint>
#include <math.h>

// Problem dims
#define BB 2
#define SS 2048
#define DD 1024
#define HH 16
#define DK 64
#define MROWS (BB * SS)   // 4096
#define BHT (BB * HH)     // 32

// -------- scratch (static __device__ globals; no allocation allowed) --------
__device__ __nv_bfloat16 g_Ph[(size_t)BB * HH * SS * SS];         // 256 MB E hi (exp scores)
__device__ __nv_bfloat16 g_Pl[(size_t)BB * HH * SS * SS];         // 256 MB E lo
__device__ float g_INV[(size_t)BHT * SS];                         // 256 KB per-row inv rowsum

// bf16 hi/lo planes
__device__ __nv_bfloat16 g_Xh[(size_t)MROWS * DD], g_Xl[(size_t)MROWS * DD];
__device__ __nv_bfloat16 g_Zh[(size_t)MROWS * DD], g_Zl[(size_t)MROWS * DD];
__device__ __nv_bfloat16 g_Qh[(size_t)MROWS * DD], g_Ql[(size_t)MROWS * DD];
__device__ __nv_bfloat16 g_Kh[(size_t)MROWS * DD], g_Kl[(size_t)MROWS * DD];
__device__ __nv_bfloat16 g_Ch[(size_t)MROWS * DD], g_Cl[(size_t)MROWS * DD];
__device__ __nv_bfloat16 g_Wqh[(size_t)DD * DD], g_Wql[(size_t)DD * DD];
__device__ __nv_bfloat16 g_Wkh[(size_t)DD * DD], g_Wkl[(size_t)DD * DD];
__device__ __nv_bfloat16 g_Woh[(size_t)DD * DD], g_Wol[(size_t)DD * DD];

// ============================================================================
// helpers
// ============================================================================
__device__ __forceinline__ uint32_t smem_u32(const void* p) {
    uint32_t a;
    asm("{ .reg .u64 t; cvta.to.shared.u64 t, %1; cvt.u32.u64 %0, t; }" : "=r"(a) : "l"(p));
    return a;
}

__device__ __forceinline__ uint32_t pack_bf16(__nv_bfloat16 a, __nv_bfloat16 b) {
    return (uint32_t)__bfloat16_as_ushort(a) | ((uint32_t)__bfloat16_as_ushort(b) << 16);
}

// cheap split: hi = truncated top-16 bits (free), lo = rn(v - hi)
__device__ __forceinline__ void split1(float v, __nv_bfloat16& h, __nv_bfloat16& l) {
    const uint32_t u = __float_as_uint(v);
    h = __ushort_as_bfloat16((unsigned short)(u >> 16));
    const float hf = __uint_as_float(u & 0xFFFF0000u);
    l = __float2bfloat16_rn(v - hf);
}

#define MMA_BF16(C, A0, A1, A2, A3, B0, B1) \
    asm volatile( \
        "mma.sync.aligned.m16n8k16.row.col.f32.bf16.bf16.f32 " \
        "{%0,%1,%2,%3}, {%4,%5,%6,%7}, {%8,%9}, {%0,%1,%2,%3};" \
        : "+f"((C)[0]), "+f"((C)[1]), "+f"((C)[2]), "+f"((C)[3]) \
        : "r"(A0), "r"(A1), "r"(A2), "r"(A3), "r"(B0), "r"(B1))

__device__ __forceinline__ void ldsm4(uint32_t* r, uint32_t addr) {
    asm volatile("ldmatrix.sync.aligned.m8n8.x4.shared.b16 {%0,%1,%2,%3}, [%4];"
        : "=r"(r[0]), "=r"(r[1]), "=r"(r[2]), "=r"(r[3]) : "r"(addr));
}
__device__ __forceinline__ void ldsm4t(uint32_t* r, uint32_t addr) {
    asm volatile("ldmatrix.sync.aligned.m8n8.x4.trans.shared.b16 {%0,%1,%2,%3}, [%4];"
        : "=r"(r[0]), "=r"(r[1]), "=r"(r[2]), "=r"(r[3]) : "r"(addr));
}

// shared-memory pitch (bf16 elements): 72 -> 144B rows -> conflict-free LDSM
#define GP 72
#define PLANE (128 * GP * 2)          // 18432 bytes per 128-row plane
#define TOFF  (16 * GP * 2)           // byte offset of 16 rows = 2304

// ============================================================================
// fused fp32 -> bf16 hi/lo split over {x, z, wq, wk, wo}
// ============================================================================
#define NX ((size_t)MROWS * DD)       // 4194304
#define NW ((size_t)DD * DD)          // 1048576

__global__ __launch_bounds__(256) void cvt_split_all(
    const float* __restrict__ x, const float* __restrict__ z,
    const float* __restrict__ wq, const float* __restrict__ wk,
    const float* __restrict__ wo)
{
    const size_t i4 = ((size_t)blockIdx.x * 256 + threadIdx.x) * 4;
    const float* src;
    __nv_bfloat16 *hi, *lo;
    if (i4 < NX)               { src = x  + i4;                 hi = g_Xh + i4;                 lo = g_Xl + i4; }
    else if (i4 < 2 * NX)      { size_t j = i4 - NX;            src = z  + j; hi = g_Zh + j;    lo = g_Zl + j; }
    else if (i4 < 2 * NX + NW) { size_t j = i4 - 2 * NX;        src = wq + j; hi = g_Wqh + j;   lo = g_Wql + j; }
    else if (i4 < 2 * NX + 2 * NW) { size_t j = i4 - 2 * NX - NW; src = wk + j; hi = g_Wkh + j; lo = g_Wkl + j; }
    else                       { size_t j = i4 - 2 * NX - 2 * NW; src = wo + j; hi = g_Woh + j; lo = g_Wol + j; }

    const float4 v = *(const float4*)src;
    __nv_bfloat16 h0, h1, h2, h3, l0, l1, l2, l3;
    split1(v.x, h0, l0); split1(v.y, h1, l1);
    split1(v.z, h2, l2); split1(v.w, h3, l3);
    uint2 ph, pl;
    ph.x = pack_bf16(h0, h1); ph.y = pack_bf16(h2, h3);
    pl.x = pack_bf16(l0, l1); pl.y = pack_bf16(l2, l3);
    *(uint2*)hi = ph;
    *(uint2*)lo = pl;
}

// ============================================================================
// bf16x3 GEMM (ldmatrix frags, reg-pipelined loads): Y = A @ W^T + bias
// 512 thr / 16 warps, CTA 128x128, warp 32x32, K-chunk 64
// ============================================================================
#define GEMM_SMEM (4 * PLANE)         // 73728

template<bool OUTF32>
__global__ void __launch_bounds__(512, 1) gemm_pre(
    const __nv_bfloat16* __restrict__ Ah_g, const __nv_bfloat16* __restrict__ Al_g,
    const __nv_bfloat16* __restrict__ Wh_g, const __nv_bfloat16* __restrict__ Wl_g,
    const float* __restrict__ bias,
    float* __restrict__ Y,
    __nv_bfloat16* __restrict__ Yh, __nv_bfloat16* __restrict__ Yl,
    int K, int N)
{
    extern __shared__ char sm[];
    const uint32_t sb = smem_u32(sm);
    __nv_bfloat16* smAh = (__nv_bfloat16*)(sm);
    __nv_bfloat16* smAl = (__nv_bfloat16*)(sm + PLANE);
    __nv_bfloat16* smWh = (__nv_bfloat16*)(sm + 2 * PLANE);
    __nv_bfloat16* smWl = (__nv_bfloat16*)(sm + 3 * PLANE);

    const int tid = threadIdx.x;
    const int lane = tid & 31;
    const int wid = tid >> 5;
    const int wy = wid >> 2;
    const int wx = wid & 3;
    const int m0 = blockIdx.y * 128;
    const int n0 = blockIdx.x * 128;

    const int srow = tid >> 2;
    const int sk0 = (tid & 3) << 4;
    const __nv_bfloat16* pAh = Ah_g + (size_t)(m0 + srow) * K + sk0;
    const __nv_bfloat16* pAl = Al_g + (size_t)(m0 + srow) * K + sk0;
    const __nv_bfloat16* pWh = Wh_g + (size_t)(n0 + srow) * K + sk0;
    const __nv_bfloat16* pWl = Wl_g + (size_t)(n0 + srow) * K + sk0;
    const int sidx = srow * GP + sk0;

    const int lr = lane & 7;
    const int lm01 = (lane >> 3) & 1;
    const int lm23 = lane >> 4;
    const uint32_t aA = sb + (uint32_t)((((wy * 32 + lm01 * 8 + lr) * GP) + lm23 * 8) << 1);
    const uint32_t aW = sb + 2 * PLANE +
        (uint32_t)((((wx * 32 + lm23 * 8 + lr) * GP) + lm01 * 8) << 1);

    float acc[2][4][4];
#pragma unroll
    for (int t = 0; t < 2; t++)
#pragma unroll
        for (int u = 0; u < 4; u++)
#pragma unroll
            for (int i = 0; i < 4; i++) acc[t][u][i] = 0.f;

    const int r8 = lane >> 2;
    const int q2 = (lane & 3) << 1;
    const int nchunk = K >> 6;

    uint4 rg[8];
    auto loadregs = [&](int c) {
        const int kc = c << 6;
        rg[0] = *(const uint4*)(pAh + kc); rg[1] = *(const uint4*)(pAh + kc + 8);
        rg[2] = *(const uint4*)(pAl + kc); rg[3] = *(const uint4*)(pAl + kc + 8);
        rg[4] = *(const uint4*)(pWh + kc); rg[5] = *(const uint4*)(pWh + kc + 8);
        rg[6] = *(const uint4*)(pWl + kc); rg[7] = *(const uint4*)(pWl + kc + 8);
    };

    loadregs(0);
    for (int c = 0; c < nchunk; c++) {
        if (c > 0) __syncthreads();
        *(uint4*)(smAh + sidx)     = rg[0]; *(uint4*)(smAh + sidx + 8) = rg[1];
        *(uint4*)(smAl + sidx)     = rg[2]; *(uint4*)(smAl + sidx + 8) = rg[3];
        *(uint4*)(smWh + sidx)     = rg[4]; *(uint4*)(smWh + sidx + 8) = rg[5];
        *(uint4*)(smWl + sidx)     = rg[6]; *(uint4*)(smWl + sidx + 8) = rg[7];
        __syncthreads();
        if (c + 1 < nchunk) loadregs(c + 1);

#pragma unroll
        for (int ks = 0; ks < 4; ks++) {
            const uint32_t kb = (uint32_t)ks << 5;
            uint32_t ahf[2][4], alf[2][4];
            ldsm4(ahf[0], aA + kb);
            ldsm4(ahf[1], aA + TOFF + kb);
            ldsm4(alf[0], aA + PLANE + kb);
            ldsm4(alf[1], aA + PLANE + TOFF + kb);
            uint32_t bhf[4][2], blf[4][2], tmp[4];
            ldsm4(tmp, aW + kb);
            bhf[0][0] = tmp[0]; bhf[0][1] = tmp[1]; bhf[1][0] = tmp[2]; bhf[1][1] = tmp[3];
            ldsm4(tmp, aW + TOFF + kb);
            bhf[2][0] = tmp[0]; bhf[2][1] = tmp[1]; bhf[3][0] = tmp[2]; bhf[3][1] = tmp[3];
            ldsm4(tmp, aW + PLANE + kb);
            blf[0][0] = tmp[0]; blf[0][1] = tmp[1]; blf[1][0] = tmp[2]; blf[1][1] = tmp[3];
            ldsm4(tmp, aW + PLANE + TOFF + kb);
            blf[2][0] = tmp[0]; blf[2][1] = tmp[1]; blf[3][0] = tmp[2]; blf[3][1] = tmp[3];
#pragma unroll
            for (int u = 0; u < 4; u++) {
#pragma unroll
                for (int t = 0; t < 2; t++) {
                    MMA_BF16(acc[t][u], ahf[t][0], ahf[t][1], ahf[t][2], ahf[t][3],
                             bhf[u][0], bhf[u][1]);
                    MMA_BF16(acc[t][u], ahf[t][0], ahf[t][1], ahf[t][2], ahf[t][3],
                             blf[u][0], blf[u][1]);
                    MMA_BF16(acc[t][u], alf[t][0], alf[t][1], alf[t][2], alf[t][3],
                             bhf[u][0], bhf[u][1]);
                }
            }
        }
    }

#pragma unroll
    for (int t = 0; t < 2; t++) {
        const int r0 = m0 + wy * 32 + t * 16 + r8;
#pragma unroll
        for (int u = 0; u < 4; u++) {
            const int col = n0 + wx * 32 + u * 8 + q2;
            const float b0 = bias[col], b1 = bias[col + 1];
            const float v00 = acc[t][u][0] + b0, v01 = acc[t][u][1] + b1;
            const float v10 = acc[t][u][2] + b0, v11 = acc[t][u][3] + b1;
            if (OUTF32) {
                *(float2*)(Y + (size_t)r0 * N + col) = make_float2(v00, v01);
                *(float2*)(Y + (size_t)(r0 + 8) * N + col) = make_float2(v10, v11);
            } else {
                __nv_bfloat16 h0, h1, l0, l1;
                split1(v00, h0, l0); split1(v01, h1, l1);
                *(uint32_t*)(Yh + (size_t)r0 * N + col) = pack_bf16(h0, h1);
                *(uint32_t*)(Yl + (size_t)r0 * N + col) = pack_bf16(l0, l1);
                split1(v10, h0, l0); split1(v11, h1, l1);
                *(uint32_t*)(Yh + (size_t)(r0 + 8) * N + col) = pack_bf16(h0, h1);
                *(uint32_t*)(Yl + (size_t)(r0 + 8) * N + col) = pack_bf16(l0, l1);
            }
        }
    }
}

// ============================================================================
// fused attention (flash-v2 register forwarding):
// per (qt256, bh) CTA, loop kt2 over 64-col K tiles.
// warp tile: 16 q-rows x 64 cols. S accumulator converts in-register into the
// A-fragment of E for MMA2 (C-frag layout == A-frag layout). No E smem; no
// cross-warp E dependency; 2 syncs per iteration (K tile reuse only).
// smem: Qh|Ql (256x64@72) | Kh|Kl (64x64@72)
// ============================================================================
#define QPLANE2 (256 * GP * 2)            // 36864
#define KBASE (2 * QPLANE2)               // 73728
#define KPLANE (64 * GP * 2)              // 9216
#define FUSED_SMEM (KBASE + 2 * KPLANE)   // 92160

__global__ void __launch_bounds__(512, 1) fused_attn(void)
{
    const int qt = 7 - blockIdx.x;                  // longest first
    const int bh = blockIdx.y;
    const int b = bh >> 4;
    const int h = bh & 15;
    const int q0 = qt << 8;                         // 256-row tiles

    extern __shared__ char sm[];
    const uint32_t sb = smem_u32(sm);
    __nv_bfloat16* Qh = (__nv_bfloat16*)(sm);
    __nv_bfloat16* Ql = (__nv_bfloat16*)(sm + QPLANE2);
    __nv_bfloat16* Kh = (__nv_bfloat16*)(sm + KBASE);
    __nv_bfloat16* Kl = (__nv_bfloat16*)(sm + KBASE + KPLANE);

    const int tid = threadIdx.x;
    const int lane = tid & 31;
    const int wid = tid >> 5;        // 0..15, warp rows = wid*16

    // stage Q once (256x64 x2 planes): thread -> (row = tid>>1, 32 cols)
    {
        const int row = tid >> 1;
        const int k0 = (tid & 1) << 5;
        const size_t qoff = ((size_t)b * SS + q0 + row) * DD + h * DK + k0;
        const int sidx = row * GP + k0;
#pragma unroll
        for (int i = 0; i < 4; i++) {
            *(uint4*)(Qh + sidx + i * 8) = *(const uint4*)(g_Qh + qoff + i * 8);
            *(uint4*)(Ql + sidx + i * 8) = *(const uint4*)(g_Ql + qoff + i * 8);
        }
    }

    const int lr = lane & 7;
    const int lm01 = (lane >> 3) & 1;
    const int lm23 = lane >> 4;
    const uint32_t aQ = sb + (uint32_t)((((wid * 16 + lm01 * 8 + lr) * GP) + lm23 * 8) << 1);
    const uint32_t aK = sb + KBASE +
        (uint32_t)((((lm23 * 8 + lr) * GP) + lm01 * 8) << 1);
    const uint32_t aV = sb + KBASE +
        (uint32_t)((((lm01 * 8 + lr) * GP) + lm23 * 8) << 1);

    const int r8 = lane >> 2;
    const int q2 = (lane & 3) << 1;
    const int row0 = q0 + wid * 16 + r8;
    const int row1 = row0 + 8;

    float accO[8][4];
#pragma unroll
    for (int u = 0; u < 8; u++)
#pragma unroll
        for (int i = 0; i < 4; i++) accO[u][i] = 0.f;
    float psum0 = 0.f, psum1 = 0.f;

    // K staging map: thread -> (krow = tid>>3, 8 d) per plane
    const int krow = tid >> 3;
    const int kd0 = (tid & 7) << 3;
    const int kidx = krow * GP + kd0;

    const int nkt = 4 * qt + 4;
    uint4 rv[2];
    auto loadK = [&](int kt2) {
        const size_t koff = ((size_t)b * SS + (kt2 << 6) + krow) * DD + h * DK + kd0;
        rv[0] = *(const uint4*)(g_Kh + koff);
        rv[1] = *(const uint4*)(g_Kl + koff);
    };

    const float scale = 0.125f;
    loadK(0);
    for (int kt2 = 0; kt2 < nkt; kt2++) {
        __syncthreads();                 // prev iter smem reads done (Q staged @0)
        *(uint4*)(Kh + kidx) = rv[0];
        *(uint4*)(Kl + kidx) = rv[1];
        __syncthreads();
        if (kt2 + 1 < nkt) loadK(kt2 + 1);

        // ---- MMA1: S = Q.K^T (warp: 16 rows x 64 cols)
        float accS[8][4];
#pragma unroll
        for (int u = 0; u < 8; u++)
#pragma unroll
            for (int i = 0; i < 4; i++) accS[u][i] = 0.f;

#pragma unroll
        for (int ks = 0; ks < 4; ks++) {
            const uint32_t kb = (uint32_t)ks << 5;
            uint32_t qh[4], ql[4];
            ldsm4(qh, aQ + kb);
            ldsm4(ql, aQ + QPLANE2 + kb);
#pragma unroll
            for (int p = 0; p < 4; p++) {
                uint32_t kh2[4], kl2[4];
                ldsm4(kh2, aK + (uint32_t)p * TOFF + kb);
                ldsm4(kl2, aK + KPLANE + (uint32_t)p * TOFF + kb);
#pragma unroll
                for (int g = 0; g < 2; g++) {
                    const int u = p * 2 + g;
                    MMA_BF16(accS[u], qh[0], qh[1], qh[2], qh[3], kh2[g * 2], kh2[g * 2 + 1]);
                    MMA_BF16(accS[u], qh[0], qh[1], qh[2], qh[3], kl2[g * 2], kl2[g * 2 + 1]);
                    MMA_BF16(accS[u], ql[0], ql[1], ql[2], ql[3], kh2[g * 2], kh2[g * 2 + 1]);
                }
            }
        }

        // ---- per 16-k-chunk: exp/mask/split -> E frags (registers) -> MMA2
        const int k0g = kt2 << 6;
#pragma unroll
        for (int c = 0; c < 4; c++) {
            uint32_t eh[4], el[4];
#pragma unroll
            for (int g = 0; g < 2; g++) {
                const int u = 2 * c + g;
                const int colg = k0g + u * 8 + q2;
                const float e00 = (colg     <= row0) ? __expf(accS[u][0] * scale) : 0.f;
                const float e01 = (colg + 1 <= row0) ? __expf(accS[u][1] * scale) : 0.f;
                const float e10 = (colg     <= row1) ? __expf(accS[u][2] * scale) : 0.f;
                const float e11 = (colg + 1 <= row1) ? __expf(accS[u][3] * scale) : 0.f;
                psum0 += e00 + e01;
                psum1 += e10 + e11;
                __nv_bfloat16 h0, h1, l0, l1, h2, h3, l2, l3;
                split1(e00, h0, l0); split1(e01, h1, l1);
                split1(e10, h2, l2); split1(e11, h3, l3);
                eh[2 * g]     = pack_bf16(h0, h1);
                eh[2 * g + 1] = pack_bf16(h2, h3);
                el[2 * g]     = pack_bf16(l0, l1);
                el[2 * g + 1] = pack_bf16(l2, l3);
                // E -> gmem planes (4B stores; L2 merges row segments)
                const size_t o0 = ((size_t)bh * SS + row0) * SS + colg;
                const size_t o1 = ((size_t)bh * SS + row1) * SS + colg;
                *(uint32_t*)(g_Ph + o0) = eh[2 * g];
                *(uint32_t*)(g_Ph + o1) = eh[2 * g + 1];
                *(uint32_t*)(g_Pl + o0) = el[2 * g];
                *(uint32_t*)(g_Pl + o1) = el[2 * g + 1];
            }
            // MMA2 chunk c: O += E @ V (V from K smem via trans)
#pragma unroll
            for (int dp = 0; dp < 4; dp++) {
                uint32_t tv[4], tl[4];
                ldsm4t(tv, aV + (uint32_t)c * TOFF + (uint32_t)dp * 32);
                ldsm4t(tl, aV + KPLANE + (uint32_t)c * TOFF + (uint32_t)dp * 32);
                MMA_BF16(accO[2 * dp],     eh[0], eh[1], eh[2], eh[3], tv[0], tv[1]);
                MMA_BF16(accO[2 * dp],     eh[0], eh[1], eh[2], eh[3], tl[0], tl[1]);
                MMA_BF16(accO[2 * dp],     el[0], el[1], el[2], el[3], tv[0], tv[1]);
                MMA_BF16(accO[2 * dp + 1], eh[0], eh[1], eh[2], eh[3], tv[2], tv[3]);
                MMA_BF16(accO[2 * dp + 1], eh[0], eh[1], eh[2], eh[3], tl[2], tl[3]);
                MMA_BF16(accO[2 * dp + 1], el[0], el[1], el[2], el[3], tv[2], tv[3]);
            }
        }
    }

    // ---- rowsum -> inv (warp-local: rows owned by this warp only)
    psum0 += __shfl_xor_sync(0xFFFFFFFFu, psum0, 1);
    psum0 += __shfl_xor_sync(0xFFFFFFFFu, psum0, 2);
    psum1 += __shfl_xor_sync(0xFFFFFFFFu, psum1, 1);
    psum1 += __shfl_xor_sync(0xFFFFFFFFu, psum1, 2);
    const float iv0 = 1.0f / psum0;
    const float iv1 = 1.0f / psum1;
    if ((lane & 3) == 0) {
        g_INV[(size_t)bh * SS + row0] = iv0;
        g_INV[(size_t)bh * SS + row1] = iv1;
    }

    // ---- O epilogue -> C bf16 planes (normalized)
#pragma unroll
    for (int u = 0; u < 8; u++) {
        const int d = u * 8 + q2;
        const size_t o0 = ((size_t)b * SS + row0) * DD + h * DK + d;
        const size_t o1 = ((size_t)b * SS + row1) * DD + h * DK + d;
        __nv_bfloat16 h0, h1, l0, l1;
        split1(accO[u][0] * iv0, h0, l0); split1(accO[u][1] * iv0, h1, l1);
        *(uint32_t*)(g_Ch + o0) = pack_bf16(h0, h1);
        *(uint32_t*)(g_Cl + o0) = pack_bf16(l0, l1);
        split1(accO[u][2] * iv1, h0, l0); split1(accO[u][3] * iv1, h1, l1);
        *(uint32_t*)(g_Ch + o1) = pack_bf16(h0, h1);
        *(uint32_t*)(g_Cl + o1) = pack_bf16(l0, l1);
    }
}

// ============================================================================
// AW[b,q,k] = sum_h E[b,h,q,k] * inv[b,h,q]; one block per (b,q)
// ============================================================================
__global__ __launch_bounds__(512) void aw_kernel(float* __restrict__ AW)
{
    const int q = blockIdx.x & (SS - 1);
    const int b = blockIdx.x >> 11;
    const int qt = q >> 7;
    const int bound = (qt + 1) << 7;

    __shared__ float inv[HH];
    const int tid = threadIdx.x;
    if (tid < HH)
        inv[tid] = g_INV[(size_t)(b * HH + tid) * SS + q];
    __syncthreads();

    float* AWrow = AW + ((size_t)b * SS + q) * SS;
    for (int k = tid << 1; k < SS; k += 1024) {
        float2 o = make_float2(0.f, 0.f);
        if (k < bound) {
#pragma unroll
            for (int h = 0; h < HH; h++) {
                const size_t off = ((size_t)(b * HH + h) * SS + q) * SS + k;
                const __nv_bfloat162 vh = *(const __nv_bfloat162*)(g_Ph + off);
                const __nv_bfloat162 vl = *(const __nv_bfloat162*)(g_Pl + off);
                const float iv = inv[h];
                o.x += (__bfloat162float(vh.x) + __bfloat162float(vl.x)) * iv;
                o.y += (__bfloat162float(vh.y) + __bfloat162float(vl.y)) * iv;
            }
        }
        *(float2*)(AWrow + k) = o;
    }
}

// ============================================================================
// launch — cvt -> {gemmQ || gemmK} -> fused_attn -> {aw || gemmO} -> join
// ============================================================================
extern "C" void kernel_launch(void* const* d_in, const int* in_sizes, int n_in,
                              void* d_out, int out_size)
{
    const float* x    = (const float*)d_in[0];
    const float* z    = (const float*)d_in[1];
    // d_in[2] = mask (causal tril; handled analytically)
    const float* wq_w = (const float*)d_in[3];
    const float* wq_b = (const float*)d_in[4];
    const float* wk_w = (const float*)d_in[5];
    const float* wk_b = (const float*)d_in[6];
    // d_in[7], d_in[8] = wv (dead param in reference: v uses wk)
    const float* wo_w = (const float*)d_in[9];
    const float* wo_b = (const float*)d_in[10];

    float* out = (float*)d_out;                              // [B,S,D]
    float* AW  = out + (size_t)BB * SS * DD;                 // [B,S,S]

    __nv_bfloat16 *pXh, *pXl, *pZh, *pZl, *pQh, *pQl, *pKh, *pKl, *pCh, *pCl;
    __nv_bfloat16 *pWqh, *pWql, *pWkh, *pWkl, *pWoh, *pWol;
    cudaGetSymbolAddress((void**)&pXh, g_Xh); cudaGetSymbolAddress((void**)&pXl, g_Xl);
    cudaGetSymbolAddress((void**)&pZh, g_Zh); cudaGetSymbolAddress((void**)&pZl, g_Zl);
    cudaGetSymbolAddress((void**)&pQh, g_Qh); cudaGetSymbolAddress((void**)&pQl, g_Ql);
    cudaGetSymbolAddress((void**)&pKh, g_Kh); cudaGetSymbolAddress((void**)&pKl, g_Kl);
    cudaGetSymbolAddress((void**)&pCh, g_Ch); cudaGetSymbolAddress((void**)&pCl, g_Cl);
    cudaGetSymbolAddress((void**)&pWqh, g_Wqh); cudaGetSymbolAddress((void**)&pWql, g_Wql);
    cudaGetSymbolAddress((void**)&pWkh, g_Wkh); cudaGetSymbolAddress((void**)&pWkl, g_Wkl);
    cudaGetSymbolAddress((void**)&pWoh, g_Woh); cudaGetSymbolAddress((void**)&pWol, g_Wol);

    static cudaStream_t s1 = nullptr;
    static cudaEvent_t e0 = nullptr, e1 = nullptr, e2 = nullptr, e3 = nullptr;
    static int smem_set = 0;
    if (!smem_set) {
        cudaFuncSetAttribute(gemm_pre<true>,  cudaFuncAttributeMaxDynamicSharedMemorySize, GEMM_SMEM);
        cudaFuncSetAttribute(gemm_pre<false>, cudaFuncAttributeMaxDynamicSharedMemorySize, GEMM_SMEM);
        cudaFuncSetAttribute(fused_attn, cudaFuncAttributeMaxDynamicSharedMemorySize, FUSED_SMEM);
        cudaStreamCreateWithFlags(&s1, cudaStreamNonBlocking);
        cudaEventCreateWithFlags(&e0, cudaEventDisableTiming);
        cudaEventCreateWithFlags(&e1, cudaEventDisableTiming);
        cudaEventCreateWithFlags(&e2, cudaEventDisableTiming);
        cudaEventCreateWithFlags(&e3, cudaEventDisableTiming);
        smem_set = 1;
    }

    // split inputs + weights (one fused launch)
    cvt_split_all<<<11264, 256>>>(x, z, wq_w, wk_w, wo_w);

    // fork: gemmQ on default, gemmK on s1
    cudaEventRecord(e0, 0);
    cudaStreamWaitEvent(s1, e0, 0);

    const dim3 gProj(DD / 128, MROWS / 128);                 // (8,32)
    gemm_pre<false><<<gProj, 512, GEMM_SMEM>>>(pXh, pXl, pWqh, pWql, wq_b,
                                               nullptr, pQh, pQl, DD, DD);
    gemm_pre<false><<<gProj, 512, GEMM_SMEM, s1>>>(pZh, pZl, pWkh, pWkl, wk_b,
                                                   nullptr, pKh, pKl, DD, DD);
    cudaEventRecord(e1, s1);
    cudaStreamWaitEvent(0, e1, 0);

    fused_attn<<<dim3(8, BHT), 512, FUSED_SMEM>>>();

    // fork: aw on s1, gemmO on default
    cudaEventRecord(e2, 0);
    cudaStreamWaitEvent(s1, e2, 0);

    aw_kernel<<<BB * SS, 512, 0, s1>>>(AW);

    gemm_pre<true><<<gProj, 512, GEMM_SMEM>>>(pCh, pCl, pWoh, pWol, wo_b,
                                              out, nullptr, nullptr, DD, DD);

    // join aw back to default stream
    cudaEventRecord(e3, s1);
    cudaStreamWaitEvent(0, e3, 0);
}